// round 16
// baseline (speedup 1.0000x reference)
#include <cuda_runtime.h>
#include <math.h>
#include <stdint.h>

#define CB   128
#define CT   288
#define CBT  (CB*CT)        // 36864
#define CU   256
#define CU3  768
#define CH   4
#define CHD  64
#define CFC  16
#define CFO  64
#define EPSF 1e-6f

// ---------------- static scratch ----------------
__device__ float g_x   [CBT*CU];
__device__ float g_tmp [CBT*CU];
__device__ float g_xg  [CBT*CU3];   // xg for GRU, then packed qkv activations
__device__ float g_o   [CBT*CU];    // attention out-proj result
__device__ float g_wqkv[CU*CU3];
__device__ float g_bqkv[CU3];
__device__ float g_pool[CB*(CU+CFO)];

// ---------------- block reductions ----------------
__device__ __forceinline__ float blk_sum(float v, float* buf){
    __syncthreads();
    int lane = threadIdx.x & 31, wid = threadIdx.x >> 5;
    #pragma unroll
    for (int o = 16; o > 0; o >>= 1) v += __shfl_down_sync(0xffffffffu, v, o);
    if (lane == 0) buf[wid] = v;
    __syncthreads();
    if (wid == 0){
        int nw = (blockDim.x + 31) >> 5;
        float r = (lane < nw) ? buf[lane] : 0.f;
        #pragma unroll
        for (int o = 16; o > 0; o >>= 1) r += __shfl_down_sync(0xffffffffu, r, o);
        if (lane == 0) buf[0] = r;
    }
    __syncthreads();
    return buf[0];
}

// ---------------- dense0 + LN0 : x = LN(cgm @ W + b) ----------------
__global__ void k_dense0(const float* __restrict__ cgm, const float* __restrict__ W,
                         const float* __restrict__ bias, const float* __restrict__ gam,
                         const float* __restrict__ bet){
    __shared__ float ws[CFC*CU];
    __shared__ float cg[CFC];
    __shared__ float red[33];
    int b = blockIdx.x, tid = threadIdx.x;
    int t0 = blockIdx.y * (CT/4);
    for (int i = tid; i < CFC*CU; i += 256) ws[i] = W[i];
    float gv = gam[tid], bv = bet[tid], biasv = bias[tid];
    __syncthreads();
    for (int t = t0; t < t0 + CT/4; ++t){
        if (tid < CFC) cg[tid] = cgm[(b*CT + t)*CFC + tid];
        __syncthreads();
        float acc = biasv;
        #pragma unroll
        for (int k = 0; k < CFC; ++k) acc += cg[k] * ws[k*CU + tid];
        float m = blk_sum(acc, red) * (1.f/CU);
        float d = acc - m;
        float var = blk_sum(d*d, red) * (1.f/CU);
        g_x[((size_t)b*CT + t)*CU + tid] = d * rsqrtf(var + EPSF) * gv + bv;
        __syncthreads();
    }
}

// ---------------- GEMM + bias: C[M,N]=A[M,K]@W[K,N]+bias ----------------
// BM=128, BN=128, BK=16, 256 threads, 8x8 per thread, reg-prefetch double buffer.
__global__ void __launch_bounds__(256, 2) k_gemm_bias(
        const float* __restrict__ A, const float* __restrict__ W,
        const float* __restrict__ bias, float* __restrict__ C,
        int M, int N, int K){
    __shared__ __align__(16) float As[16][128];
    __shared__ __align__(16) float Bs[16][132];
    int tid = threadIdx.x;
    int tx = tid & 15, ty = tid >> 4;
    int bm = blockIdx.y * 128, bn = blockIdx.x * 128;

    float acc[8][8];
    #pragma unroll
    for (int i = 0; i < 8; ++i)
        #pragma unroll
        for (int j = 0; j < 8; ++j) acc[i][j] = 0.f;

    float4 ra[2], rb[2];
    #pragma unroll
    for (int q = 0; q < 2; ++q){
        int i = tid + (q << 8);
        int m = i >> 2, kk = (i & 3) << 2;
        ra[q] = *(const float4*)(A + (size_t)(bm + m)*K + kk);
        int kb = i >> 5, n4 = (i & 31) << 2;
        rb[q] = *(const float4*)(W + (size_t)kb*N + bn + n4);
    }

    for (int k0 = 0; k0 < K; k0 += 16){
        #pragma unroll
        for (int q = 0; q < 2; ++q){
            int i = tid + (q << 8);
            int m = i >> 2, kk = (i & 3) << 2;
            As[kk+0][m] = ra[q].x; As[kk+1][m] = ra[q].y;
            As[kk+2][m] = ra[q].z; As[kk+3][m] = ra[q].w;
            int kb = i >> 5, n4 = (i & 31) << 2;
            *(float4*)&Bs[kb][n4] = rb[q];
        }
        __syncthreads();
        if (k0 + 16 < K){
            #pragma unroll
            for (int q = 0; q < 2; ++q){
                int i = tid + (q << 8);
                int m = i >> 2, kk = (i & 3) << 2;
                ra[q] = *(const float4*)(A + (size_t)(bm + m)*K + k0 + 16 + kk);
                int kb = i >> 5, n4 = (i & 31) << 2;
                rb[q] = *(const float4*)(W + (size_t)(k0 + 16 + kb)*N + bn + n4);
            }
        }
        #pragma unroll
        for (int kk = 0; kk < 16; ++kk){
            float a[8], bb[8];
            *(float4*)&a[0]  = *(const float4*)&As[kk][ty*8];
            *(float4*)&a[4]  = *(const float4*)&As[kk][ty*8 + 4];
            *(float4*)&bb[0] = *(const float4*)&Bs[kk][tx*8];
            *(float4*)&bb[4] = *(const float4*)&Bs[kk][tx*8 + 4];
            #pragma unroll
            for (int i = 0; i < 8; ++i)
                #pragma unroll
                for (int j = 0; j < 8; ++j)
                    acc[i][j] += a[i] * bb[j];
        }
        __syncthreads();
    }

    float4 bv0 = *(const float4*)(bias + bn + tx*8);
    float4 bv1 = *(const float4*)(bias + bn + tx*8 + 4);
    #pragma unroll
    for (int i = 0; i < 8; ++i){
        size_t row = (size_t)(bm + ty*8 + i)*N + bn + tx*8;
        float4 o0 = make_float4(acc[i][0]+bv0.x, acc[i][1]+bv0.y, acc[i][2]+bv0.z, acc[i][3]+bv0.w);
        float4 o1 = make_float4(acc[i][4]+bv1.x, acc[i][5]+bv1.y, acc[i][6]+bv1.z, acc[i][7]+bv1.w);
        *(float4*)&C[row]     = o0;
        *(float4*)&C[row + 4] = o1;
    }
}

// ---------------- pack Wq|Wk|Wv -> g_wqkv, bq|bk|bv -> g_bqkv ----------------
__global__ void k_pack(const float* __restrict__ Wq, const float* __restrict__ Wk,
                       const float* __restrict__ Wv, const float* __restrict__ bq,
                       const float* __restrict__ bk, const float* __restrict__ bv){
    int i = blockIdx.x*blockDim.x + threadIdx.x;
    if (i < CU*CU3){
        int k = i / CU3, n = i % CU3;
        float v = (n < CU) ? Wq[k*CU + n]
                : (n < 2*CU) ? Wk[k*CU + n - CU]
                             : Wv[k*CU + n - 2*CU];
        g_wqkv[i] = v;
    }
    if (i < CU3)
        g_bqkv[i] = (i < CU) ? bq[i] : (i < 2*CU) ? bk[i-CU] : bv[i-2*CU];
}

// ---------------- GRU: cluster-4 DSMEM recurrence (one layer) ----------------
// 32 clusters x 4 CTAs. Cluster owns 4 batches; CTA rank owns u in [64r, 64r+64).
// smem per CTA: Wr/Wz/Wn planes [64][260] (conflict-free) + hs[2][4][260].
// Per step: FFMA dot; h broadcast to all 4 CTAs' smem via mapa+st.shared::cluster;
// one barrier.cluster (arrive=release, wait=acquire). No global h, no threadfence.
#define WPLN (64*260)
#define HROW 260
__global__ void __launch_bounds__(256) __cluster_dims__(4, 1, 1)
k_gru(const float* __restrict__ Wh, const float* __restrict__ bhn){
    extern __shared__ float sm[];
    float* Wr = sm;
    float* Wz = sm + WPLN;
    float* Wn = sm + 2*WPLN;
    float* hsbuf = sm + 3*WPLN;          // [2][4][260]
    int tid = threadIdx.x;
    int rank = blockIdx.x & 3;
    int b0 = (blockIdx.x >> 2) * 4;
    int u0 = rank * 64;
    int bl = tid >> 6, ul = tid & 63;
    int b = b0 + bl, u = u0 + ul;

    // load this CTA's 64 Wh columns, [u][k] layout, row stride 260
    {
        int uu = tid & 63;
        int kb = tid >> 6;
        for (int j = 0; j < 64; ++j){
            int k = kb + j*4;
            Wr[uu*HROW + k] = Wh[(size_t)k*CU3 + u0 + uu];
            Wz[uu*HROW + k] = Wh[(size_t)k*CU3 + CU + u0 + uu];
            Wn[uu*HROW + k] = Wh[(size_t)k*CU3 + 2*CU + u0 + uu];
        }
    }
    for (int i = tid; i < 2*4*HROW; i += 256) hsbuf[i] = 0.f;   // h0 = 0
    float bh = bhn[u];
    __syncthreads();
    asm volatile("barrier.cluster.arrive.aligned;" ::: "memory");
    asm volatile("barrier.cluster.wait.aligned;"   ::: "memory");

    uint32_t hs_addr;
    asm("{ .reg .u64 t; cvta.to.shared.u64 t, %1; cvt.u32.u64 %0, t; }"
        : "=r"(hs_addr) : "l"(hsbuf));

    const float* wr = Wr + ul*HROW;
    const float* wz = Wz + ul*HROW;
    const float* wn = Wn + ul*HROW;

    for (int t = 0; t < CT; ++t){
        int cb = t & 1;
        const float* hrow = hsbuf + cb*(4*HROW) + bl*HROW;
        size_t xb = ((size_t)b*CT + t)*CU3 + u;
        float xr = __ldg(&g_xg[xb]);
        float xz = __ldg(&g_xg[xb + CU]);
        float xn = __ldg(&g_xg[xb + 2*CU]);
        float ar = 0.f, az = 0.f, an = 0.f;
        #pragma unroll 8
        for (int k = 0; k < CU; k += 4){
            float4 hv = *(const float4*)&hrow[k];
            float4 r4 = *(const float4*)&wr[k];
            float4 z4 = *(const float4*)&wz[k];
            float4 n4 = *(const float4*)&wn[k];
            ar += hv.x*r4.x + hv.y*r4.y + hv.z*r4.z + hv.w*r4.w;
            az += hv.x*z4.x + hv.y*z4.y + hv.z*z4.z + hv.w*z4.w;
            an += hv.x*n4.x + hv.y*n4.y + hv.z*n4.z + hv.w*n4.w;
        }
        float r = 1.f/(1.f + __expf(-(xr + ar)));
        float z = 1.f/(1.f + __expf(-(xz + az)));
        float n = tanhf(xn + r*(an + bh));
        float hn = (1.f - z)*n + z*hrow[u];
        g_tmp[((size_t)b*CT + t)*CU + u] = hn;

        // write h' into next buffer of ALL 4 cluster CTAs (incl. self) via DSMEM
        uint32_t loff = hs_addr + (uint32_t)(((cb ^ 1)*4 + bl)*HROW + u) * 4u;
        #pragma unroll
        for (int rd = 0; rd < 4; ++rd){
            uint32_t raddr;
            asm("mapa.shared::cluster.u32 %0, %1, %2;" : "=r"(raddr) : "r"(loff), "r"(rd));
            asm volatile("st.shared::cluster.f32 [%0], %1;" :: "r"(raddr), "f"(hn) : "memory");
        }
        asm volatile("barrier.cluster.arrive.aligned;" ::: "memory");
        asm volatile("barrier.cluster.wait.aligned;"   ::: "memory");
    }
}

// ---------------- LN + residual ----------------
// mode 0: x = LN(a)*g+b + x   ; mode 1: x = LN(a + x)*g+b
__global__ void k_ln_res(const float* __restrict__ a, const float* __restrict__ gam,
                         const float* __restrict__ bet, int mode){
    __shared__ float red[33];
    size_t r = blockIdx.x;
    int u = threadIdx.x;
    float av = a[r*CU + u], xv = g_x[r*CU + u];
    float v = mode ? (av + xv) : av;
    float m = blk_sum(v, red) * (1.f/CU);
    float d = v - m;
    float var = blk_sum(d*d, red) * (1.f/CU);
    float ln = d * rsqrtf(var + EPSF) * gam[u] + bet[u];
    g_x[r*CU + u] = mode ? ln : (ln + xv);
}

// ---------------- fused flash attention ----------------
// grid (CT/16, CB*CH), block 128. qkv packed in g_xg rows (stride 768):
// q at [h*64], k at [256+h*64], v at [512+h*64]. Output -> g_tmp [BT,256].
__global__ void __launch_bounds__(128) k_flash(){
    __shared__ __align__(16) float Qs[16][68];
    __shared__ __align__(16) float Ks[32][68];
    __shared__ __align__(16) float Vs[32][68];
    __shared__ float Ss[16][33];
    int tid = threadIdx.x;
    int b = blockIdx.y >> 2, h = blockIdx.y & 3;
    int q0 = blockIdx.x * 16;
    int qi = tid >> 3;
    int kc = (tid & 7) << 2;
    int dc = (tid & 7) << 3;

    for (int i = tid; i < 256; i += 128){
        int r = i >> 4, d4 = (i & 15) << 2;
        *(float4*)&Qs[r][d4] =
            *(const float4*)&g_xg[((size_t)(b*CT) + q0 + r)*CU3 + h*CHD + d4];
    }
    float acc[8];
    #pragma unroll
    for (int j = 0; j < 8; ++j) acc[j] = 0.f;
    float mrow = -3.0e38f, lrow = 0.f;

    for (int kt = 0; kt < CT; kt += 32){
        for (int i = tid; i < 512; i += 128){
            int r = i >> 4, d4 = (i & 15) << 2;
            size_t base = ((size_t)(b*CT) + kt + r)*CU3 + h*CHD + d4;
            *(float4*)&Ks[r][d4] = *(const float4*)&g_xg[base + CU];
            *(float4*)&Vs[r][d4] = *(const float4*)&g_xg[base + 2*CU];
        }
        __syncthreads();
        #pragma unroll
        for (int kk = 0; kk < 4; ++kk){
            int k = kc + kk;
            float s = 0.f;
            #pragma unroll
            for (int d = 0; d < 64; d += 4){
                float4 qv = *(const float4*)&Qs[qi][d];
                float4 kv = *(const float4*)&Ks[k][d];
                s += qv.x*kv.x + qv.y*kv.y + qv.z*kv.z + qv.w*kv.w;
            }
            Ss[qi][k] = s * 0.125f;
        }
        __syncthreads();
        float cm = -3.0e38f;
        #pragma unroll
        for (int j = 0; j < 32; ++j) cm = fmaxf(cm, Ss[qi][j]);
        float nm = fmaxf(mrow, cm);
        float corr = __expf(mrow - nm);
        lrow *= corr;
        #pragma unroll
        for (int j = 0; j < 8; ++j) acc[j] *= corr;
        #pragma unroll 4
        for (int j = 0; j < 32; ++j){
            float p = __expf(Ss[qi][j] - nm);
            lrow += p;
            float4 v0 = *(const float4*)&Vs[j][dc];
            float4 v1 = *(const float4*)&Vs[j][dc + 4];
            acc[0] += p*v0.x; acc[1] += p*v0.y; acc[2] += p*v0.z; acc[3] += p*v0.w;
            acc[4] += p*v1.x; acc[5] += p*v1.y; acc[6] += p*v1.z; acc[7] += p*v1.w;
        }
        mrow = nm;
        __syncthreads();
    }
    float inv = 1.f / lrow;
    size_t orow = ((size_t)(b*CT) + q0 + qi)*CU + h*CHD + dc;
    float4 o0 = make_float4(acc[0]*inv, acc[1]*inv, acc[2]*inv, acc[3]*inv);
    float4 o1 = make_float4(acc[4]*inv, acc[5]*inv, acc[6]*inv, acc[7]*inv);
    *(float4*)&g_tmp[orow]     = o0;
    *(float4*)&g_tmp[orow + 4] = o1;
}

// ---------------- mean pool over T + concat other ----------------
__global__ void k_pool(const float* __restrict__ other){
    int b = blockIdx.x, u = threadIdx.x;
    float s = 0.f;
    #pragma unroll 4
    for (int t = 0; t < CT; ++t) s += g_x[((size_t)b*CT + t)*CU + u];
    g_pool[b*(CU+CFO) + u] = s * (1.f/CT);
    if (u < CFO) g_pool[b*(CU+CFO) + CU + u] = other[b*CFO + u];
}

// ---------------- MLP head ----------------
__global__ void k_head(const float* __restrict__ m1W, const float* __restrict__ m1b,
                       const float* __restrict__ l1s, const float* __restrict__ l1b,
                       const float* __restrict__ m2W, const float* __restrict__ m2b,
                       const float* __restrict__ l2s, const float* __restrict__ l2b,
                       const float* __restrict__ oW, const float* __restrict__ ob,
                       float* __restrict__ out){
    __shared__ float ps[320];
    __shared__ float h1s[128];
    __shared__ float red[33];
    int b = blockIdx.x, j = threadIdx.x;
    for (int i = j; i < 320; i += 128) ps[i] = g_pool[b*320 + i];
    __syncthreads();
    float a = m1b[j];
    for (int k = 0; k < 320; ++k) a += ps[k] * m1W[k*128 + j];
    a = fmaxf(a, 0.f);
    float m = blk_sum(a, red) * (1.f/128.f);
    float d = a - m;
    float var = blk_sum(d*d, red) * (1.f/128.f);
    h1s[j] = d * rsqrtf(var + EPSF) * l1s[j] + l1b[j];
    __syncthreads();
    float a2 = 0.f;
    if (j < 64){
        a2 = m2b[j];
        for (int k = 0; k < 128; ++k) a2 += h1s[k] * m2W[k*64 + j];
        a2 = fmaxf(a2, 0.f);
    }
    float m2v = blk_sum((j < 64) ? a2 : 0.f, red) * (1.f/64.f);
    float d2 = a2 - m2v;
    float var2 = blk_sum((j < 64) ? d2*d2 : 0.f, red) * (1.f/64.f);
    float contrib = 0.f;
    if (j < 64){
        float h2 = d2 * rsqrtf(var2 + EPSF) * l2s[j] + l2b[j];
        contrib = h2 * oW[j];
    }
    float o = blk_sum(contrib, red);
    if (j == 0) out[b] = o + ob[0];
}

// ---------------- launch ----------------
extern "C" void kernel_launch(void* const* d_in, const int* in_sizes, int n_in,
                              void* d_out, int out_size){
    const float* cgm    = (const float*)d_in[0];
    const float* other  = (const float*)d_in[1];
    const float* d0_W   = (const float*)d_in[2];
    const float* d0_b   = (const float*)d_in[3];
    const float* ln0_s  = (const float*)d_in[4];
    const float* ln0_b  = (const float*)d_in[5];
    const float* gru_Wi = (const float*)d_in[6];
    const float* gru_bi = (const float*)d_in[7];
    const float* gru_Wh = (const float*)d_in[8];
    const float* gru_bhn= (const float*)d_in[9];
    const float* ln1_s  = (const float*)d_in[10];
    const float* ln1_b  = (const float*)d_in[11];
    const float* Wq     = (const float*)d_in[12];
    const float* bq     = (const float*)d_in[13];
    const float* Wk     = (const float*)d_in[14];
    const float* bk     = (const float*)d_in[15];
    const float* Wv     = (const float*)d_in[16];
    const float* bv     = (const float*)d_in[17];
    const float* Wo     = (const float*)d_in[18];
    const float* bo     = (const float*)d_in[19];
    const float* ln2_s  = (const float*)d_in[20];
    const float* ln2_b  = (const float*)d_in[21];
    const float* m1_W   = (const float*)d_in[22];
    const float* m1_b   = (const float*)d_in[23];
    const float* lm1_s  = (const float*)d_in[24];
    const float* lm1_b  = (const float*)d_in[25];
    const float* m2_W   = (const float*)d_in[26];
    const float* m2_b   = (const float*)d_in[27];
    const float* lm2_s  = (const float*)d_in[28];
    const float* lm2_b  = (const float*)d_in[29];
    const float* out_W  = (const float*)d_in[30];
    const float* out_b  = (const float*)d_in[31];
    float* outp = (float*)d_out;

    float *px, *ptmp, *pxg, *po, *pwq, *pbq;
    cudaGetSymbolAddress((void**)&px,   g_x);
    cudaGetSymbolAddress((void**)&ptmp, g_tmp);
    cudaGetSymbolAddress((void**)&pxg,  g_xg);
    cudaGetSymbolAddress((void**)&po,   g_o);
    cudaGetSymbolAddress((void**)&pwq,  g_wqkv);
    cudaGetSymbolAddress((void**)&pbq,  g_bqkv);

    const int GRU_SMEM = (3*WPLN + 2*4*HROW) * 4;   // 199.7KB + 8.3KB = 208000B
    cudaFuncSetAttribute(k_gru, cudaFuncAttributeMaxDynamicSharedMemorySize, GRU_SMEM);

    k_dense0<<<dim3(CB,4), 256>>>(cgm, d0_W, d0_b, ln0_s, ln0_b);

    for (int i = 0; i < 2; ++i){
        // xg = x @ Wi + bi  -> g_xg
        k_gemm_bias<<<dim3(CU3/128, CBT/128), 256>>>(px, gru_Wi + (size_t)i*CU*CU3,
                                                     gru_bi + i*CU3, pxg, CBT, CU3, CU);
        // GRU recurrence -> g_tmp (cluster-4 DSMEM, no grid barrier)
        k_gru<<<128, 256, GRU_SMEM>>>(gru_Wh + (size_t)i*CU*CU3, gru_bhn + i*CU);
        // x = LN(ys) + x
        k_ln_res<<<CBT, 256>>>(ptmp, ln1_s + i*CU, ln1_b + i*CU, 0);
        // packed qkv GEMM -> g_xg
        k_pack<<<(CU*CU3 + 255)/256, 256>>>(Wq + (size_t)i*CU*CU, Wk + (size_t)i*CU*CU,
                                            Wv + (size_t)i*CU*CU, bq + i*CU, bk + i*CU, bv + i*CU);
        k_gemm_bias<<<dim3(CU3/128, CBT/128), 256>>>(px, pwq, pbq, pxg, CBT, CU3, CU);
        // fused attention -> g_tmp
        k_flash<<<dim3(CT/16, CB*CH), 128>>>();
        // out proj -> g_o, then x = LN(attn + x)
        k_gemm_bias<<<dim3(CU/128, CBT/128), 256>>>(ptmp, Wo + (size_t)i*CU*CU,
                                                    bo + i*CU, po, CBT, CU, CU);
        k_ln_res<<<CBT, 256>>>(po, ln2_s + i*CU, ln2_b + i*CU, 1);
    }

    k_pool<<<CB, 256>>>(other);
    k_head<<<CB, 128>>>(m1_W, m1_b, lm1_s, lm1_b, m2_W, m2_b, lm2_s, lm2_b, out_W, out_b, outp);
}

// round 17
// speedup vs baseline: 1.3135x; 1.3135x over previous
#include <cuda_runtime.h>
#include <math.h>
#include <stdint.h>

#define CB   128
#define CT   288
#define CBT  (CB*CT)        // 36864
#define CU   256
#define CU3  768
#define CH   4
#define CHD  64
#define CFC  16
#define CFO  64
#define EPSF 1e-6f

// ---------------- static scratch ----------------
__device__ float g_x   [CBT*CU];
__device__ float g_tmp [CBT*CU];
__device__ float g_xg  [CBT*CU3];   // xg for GRU, then packed qkv activations
__device__ float g_o   [CBT*CU];    // attention out-proj result
__device__ float g_wqkv[CU*CU3];
__device__ float g_bqkv[CU3];
__device__ float g_h   [2][CB*CU];
__device__ float g_pool[CB*(CU+CFO)];
__device__ unsigned g_bar_cnt;      // accumulating arrival counter
__device__ unsigned g_bar_gen;      // release generation word

// ---------------- block reductions ----------------
__device__ __forceinline__ float blk_sum(float v, float* buf){
    __syncthreads();
    int lane = threadIdx.x & 31, wid = threadIdx.x >> 5;
    #pragma unroll
    for (int o = 16; o > 0; o >>= 1) v += __shfl_down_sync(0xffffffffu, v, o);
    if (lane == 0) buf[wid] = v;
    __syncthreads();
    if (wid == 0){
        int nw = (blockDim.x + 31) >> 5;
        float r = (lane < nw) ? buf[lane] : 0.f;
        #pragma unroll
        for (int o = 16; o > 0; o >>= 1) r += __shfl_down_sync(0xffffffffu, r, o);
        if (lane == 0) buf[0] = r;
    }
    __syncthreads();
    return buf[0];
}

// ---------------- dense0 + LN0 : x = LN(cgm @ W + b) ----------------
__global__ void k_dense0(const float* __restrict__ cgm, const float* __restrict__ W,
                         const float* __restrict__ bias, const float* __restrict__ gam,
                         const float* __restrict__ bet){
    __shared__ float ws[CFC*CU];
    __shared__ float cg[CFC];
    __shared__ float red[33];
    int b = blockIdx.x, tid = threadIdx.x;
    int t0 = blockIdx.y * (CT/4);
    for (int i = tid; i < CFC*CU; i += 256) ws[i] = W[i];
    float gv = gam[tid], bv = bet[tid], biasv = bias[tid];
    __syncthreads();
    for (int t = t0; t < t0 + CT/4; ++t){
        if (tid < CFC) cg[tid] = cgm[(b*CT + t)*CFC + tid];
        __syncthreads();
        float acc = biasv;
        #pragma unroll
        for (int k = 0; k < CFC; ++k) acc += cg[k] * ws[k*CU + tid];
        float m = blk_sum(acc, red) * (1.f/CU);
        float d = acc - m;
        float var = blk_sum(d*d, red) * (1.f/CU);
        g_x[((size_t)b*CT + t)*CU + tid] = d * rsqrtf(var + EPSF) * gv + bv;
        __syncthreads();
    }
}

// ---------------- GEMM + bias: C[M,N]=A[M,K]@W[K,N]+bias ----------------
// BM=128, BN=128, BK=16, 256 threads, 8x8 per thread, reg-prefetch double buffer.
__global__ void __launch_bounds__(256, 2) k_gemm_bias(
        const float* __restrict__ A, const float* __restrict__ W,
        const float* __restrict__ bias, float* __restrict__ C,
        int M, int N, int K){
    __shared__ __align__(16) float As[16][128];
    __shared__ __align__(16) float Bs[16][132];
    int tid = threadIdx.x;
    int tx = tid & 15, ty = tid >> 4;
    int bm = blockIdx.y * 128, bn = blockIdx.x * 128;

    float acc[8][8];
    #pragma unroll
    for (int i = 0; i < 8; ++i)
        #pragma unroll
        for (int j = 0; j < 8; ++j) acc[i][j] = 0.f;

    float4 ra[2], rb[2];
    #pragma unroll
    for (int q = 0; q < 2; ++q){
        int i = tid + (q << 8);
        int m = i >> 2, kk = (i & 3) << 2;
        ra[q] = *(const float4*)(A + (size_t)(bm + m)*K + kk);
        int kb = i >> 5, n4 = (i & 31) << 2;
        rb[q] = *(const float4*)(W + (size_t)kb*N + bn + n4);
    }

    for (int k0 = 0; k0 < K; k0 += 16){
        #pragma unroll
        for (int q = 0; q < 2; ++q){
            int i = tid + (q << 8);
            int m = i >> 2, kk = (i & 3) << 2;
            As[kk+0][m] = ra[q].x; As[kk+1][m] = ra[q].y;
            As[kk+2][m] = ra[q].z; As[kk+3][m] = ra[q].w;
            int kb = i >> 5, n4 = (i & 31) << 2;
            *(float4*)&Bs[kb][n4] = rb[q];
        }
        __syncthreads();
        if (k0 + 16 < K){
            #pragma unroll
            for (int q = 0; q < 2; ++q){
                int i = tid + (q << 8);
                int m = i >> 2, kk = (i & 3) << 2;
                ra[q] = *(const float4*)(A + (size_t)(bm + m)*K + k0 + 16 + kk);
                int kb = i >> 5, n4 = (i & 31) << 2;
                rb[q] = *(const float4*)(W + (size_t)(k0 + 16 + kb)*N + bn + n4);
            }
        }
        #pragma unroll
        for (int kk = 0; kk < 16; ++kk){
            float a[8], bb[8];
            *(float4*)&a[0]  = *(const float4*)&As[kk][ty*8];
            *(float4*)&a[4]  = *(const float4*)&As[kk][ty*8 + 4];
            *(float4*)&bb[0] = *(const float4*)&Bs[kk][tx*8];
            *(float4*)&bb[4] = *(const float4*)&Bs[kk][tx*8 + 4];
            #pragma unroll
            for (int i = 0; i < 8; ++i)
                #pragma unroll
                for (int j = 0; j < 8; ++j)
                    acc[i][j] += a[i] * bb[j];
        }
        __syncthreads();
    }

    float4 bv0 = *(const float4*)(bias + bn + tx*8);
    float4 bv1 = *(const float4*)(bias + bn + tx*8 + 4);
    #pragma unroll
    for (int i = 0; i < 8; ++i){
        size_t row = (size_t)(bm + ty*8 + i)*N + bn + tx*8;
        float4 o0 = make_float4(acc[i][0]+bv0.x, acc[i][1]+bv0.y, acc[i][2]+bv0.z, acc[i][3]+bv0.w);
        float4 o1 = make_float4(acc[i][4]+bv1.x, acc[i][5]+bv1.y, acc[i][6]+bv1.z, acc[i][7]+bv1.w);
        *(float4*)&C[row]     = o0;
        *(float4*)&C[row + 4] = o1;
    }
}

// ---------------- pack Wq|Wk|Wv -> g_wqkv, bq|bk|bv -> g_bqkv ----------------
__global__ void k_pack(const float* __restrict__ Wq, const float* __restrict__ Wk,
                       const float* __restrict__ Wv, const float* __restrict__ bq,
                       const float* __restrict__ bk, const float* __restrict__ bv){
    int i = blockIdx.x*blockDim.x + threadIdx.x;
    if (i < CU*CU3){
        int k = i / CU3, n = i % CU3;
        float v = (n < CU) ? Wq[k*CU + n]
                : (n < 2*CU) ? Wk[k*CU + n - CU]
                             : Wv[k*CU + n - 2*CU];
        g_wqkv[i] = v;
    }
    if (i < CU3)
        g_bqkv[i] = (i < CU) ? bq[i] : (i < 2*CU) ? bk[i-CU] : bv[i-2*CU];
}

// ---------------- GRU init: h0 = 0, barrier reset ----------------
__global__ void k_gru_init(){
    int i = blockIdx.x*blockDim.x + threadIdx.x;
    if (i < CB*CU) g_h[0][i] = 0.f;
    if (i == 0){ g_bar_cnt = 0u; g_bar_gen = 0u; }
}

// ---------------- GRU persistent kernel (one layer) ----------------
// 128 CTAs = 4 batch-tiles(32) x 32 u-tiles(8).
// smem: Wg float4[256*8] = 32KB ; hs float[32][260]
// Grid barrier WITHOUT membar: bar.sync orders CTA stores; tid0 arrives with
// atom.acq_rel.gpu (cumulative release); last arriver publishes gen with
// st.release.gpu; waiters poll with ld.acquire.gpu. No __threadfence anywhere.
__global__ void __launch_bounds__(256) k_gru(const float* __restrict__ Wh,
                                             const float* __restrict__ bhn){
    extern __shared__ float sm[];
    float4* Wg = (float4*)sm;
    float*  hs = sm + 8192;
    int tid = threadIdx.x;
    int bl = tid >> 3, ul = tid & 7;
    int b0 = (blockIdx.x >> 5) * 32;
    int u0 = (blockIdx.x & 31) * 8;
    int b = b0 + bl, u = u0 + ul;
    for (int i = tid; i < 2048; i += 256){
        int k = i >> 3, uu = i & 7;
        Wg[i] = make_float4(Wh[k*CU3 + u0 + uu],
                            Wh[k*CU3 + CU + u0 + uu],
                            Wh[k*CU3 + 2*CU + u0 + uu], 0.f);
    }
    float bh = bhn[u];
    __syncthreads();

    // prefetch xg for t=0
    size_t xrow = ((size_t)b*CT)*CU3 + u;
    float xr = __ldg(&g_xg[xrow]);
    float xz = __ldg(&g_xg[xrow + CU]);
    float xn = __ldg(&g_xg[xrow + 2*CU]);

    for (int t = 0; t < CT; ++t){
        int cur = t & 1;
        for (int i = tid; i < 512; i += 256){
            int bb = i >> 4, k4 = (i & 15) << 4;
            *(float4*)&hs[bb*260 + k4] =
                __ldcg((const float4*)&g_h[cur][(size_t)(b0+bb)*CU + k4]);
            *(float4*)&hs[bb*260 + k4 + 4] =
                __ldcg((const float4*)&g_h[cur][(size_t)(b0+bb)*CU + k4 + 4]);
            *(float4*)&hs[bb*260 + k4 + 8] =
                __ldcg((const float4*)&g_h[cur][(size_t)(b0+bb)*CU + k4 + 8]);
            *(float4*)&hs[bb*260 + k4 + 12] =
                __ldcg((const float4*)&g_h[cur][(size_t)(b0+bb)*CU + k4 + 12]);
        }
        __syncthreads();
        const float* hrow = hs + bl*260;
        float ar = 0.f, az = 0.f, an = 0.f;
        #pragma unroll 4
        for (int k = 0; k < CU; k += 4){
            float4 hv = *(const float4*)&hrow[k];
            float4 w0 = Wg[(k+0)*8 + ul];
            float4 w1 = Wg[(k+1)*8 + ul];
            float4 w2 = Wg[(k+2)*8 + ul];
            float4 w3 = Wg[(k+3)*8 + ul];
            ar += hv.x*w0.x + hv.y*w1.x + hv.z*w2.x + hv.w*w3.x;
            az += hv.x*w0.y + hv.y*w1.y + hv.z*w2.y + hv.w*w3.y;
            an += hv.x*w0.z + hv.y*w1.z + hv.z*w2.z + hv.w*w3.z;
        }
        float r = 1.f/(1.f + __expf(-(xr + ar)));
        float z = 1.f/(1.f + __expf(-(xz + az)));
        float n = tanhf(xn + r*(an + bh));
        float hn = (1.f - z)*n + z*hrow[u];
        g_h[cur ^ 1][(size_t)b*CU + u] = hn;
        g_tmp[((size_t)b*CT + t)*CU + u] = hn;

        // prefetch next step's xg (overlaps the barrier wait)
        if (t + 1 < CT){
            size_t xb2 = xrow + (size_t)(t + 1)*CU3;
            xr = __ldg(&g_xg[xb2]);
            xz = __ldg(&g_xg[xb2 + CU]);
            xn = __ldg(&g_xg[xb2 + 2*CU]);
        }

        // ---- grid barrier (release/acquire, no MEMBAR) ----
        __syncthreads();                  // CTA-order all h stores before arrive
        if (tid == 0){
            unsigned tgt = (unsigned)(t + 1);
            unsigned v;
            asm volatile("atom.acq_rel.gpu.global.add.u32 %0, [%1], %2;"
                         : "=r"(v) : "l"(&g_bar_cnt), "r"(1u) : "memory");
            if (v == tgt * 128u - 1u){
                asm volatile("st.release.gpu.global.u32 [%0], %1;"
                             :: "l"(&g_bar_gen), "r"(tgt) : "memory");
            }
            for (;;){
                unsigned gv;
                asm volatile("ld.acquire.gpu.global.u32 %0, [%1];"
                             : "=r"(gv) : "l"(&g_bar_gen) : "memory");
                if (gv >= tgt) break;
                __nanosleep(32);
            }
        }
        __syncthreads();                  // propagate tid0's acquire to the CTA
    }
}

// ---------------- LN + residual (warp per row) ----------------
// mode 0: x = LN(a)*g+b + x   ; mode 1: x = LN(a + x)*g+b
// grid = CBT/8, block 256 (8 warps = 8 rows).
__global__ void __launch_bounds__(256) k_ln_res(const float* __restrict__ a,
                                                const float* __restrict__ gam,
                                                const float* __restrict__ bet, int mode){
    int w = threadIdx.x >> 5, lane = threadIdx.x & 31;
    size_t r = (size_t)blockIdx.x*8 + w;
    size_t base = r*CU + lane*8;
    float4 av0 = *(const float4*)&a[base];
    float4 av1 = *(const float4*)&a[base + 4];
    float4 xv0 = *(const float4*)&g_x[base];
    float4 xv1 = *(const float4*)&g_x[base + 4];
    float v[8], xv[8];
    xv[0]=xv0.x; xv[1]=xv0.y; xv[2]=xv0.z; xv[3]=xv0.w;
    xv[4]=xv1.x; xv[5]=xv1.y; xv[6]=xv1.z; xv[7]=xv1.w;
    float avv[8] = {av0.x,av0.y,av0.z,av0.w,av1.x,av1.y,av1.z,av1.w};
    #pragma unroll
    for (int i = 0; i < 8; ++i) v[i] = mode ? (avv[i] + xv[i]) : avv[i];
    float s = 0.f;
    #pragma unroll
    for (int i = 0; i < 8; ++i) s += v[i];
    #pragma unroll
    for (int o = 16; o > 0; o >>= 1) s += __shfl_xor_sync(0xffffffffu, s, o);
    float m = s * (1.f/CU);
    float vs = 0.f;
    #pragma unroll
    for (int i = 0; i < 8; ++i){ float d = v[i] - m; vs += d*d; }
    #pragma unroll
    for (int o = 16; o > 0; o >>= 1) vs += __shfl_xor_sync(0xffffffffu, vs, o);
    float inv = rsqrtf(vs * (1.f/CU) + EPSF);
    float4 g0 = *(const float4*)&gam[lane*8];
    float4 g1 = *(const float4*)&gam[lane*8 + 4];
    float4 b0 = *(const float4*)&bet[lane*8];
    float4 b1 = *(const float4*)&bet[lane*8 + 4];
    float gg[8] = {g0.x,g0.y,g0.z,g0.w,g1.x,g1.y,g1.z,g1.w};
    float bb[8] = {b0.x,b0.y,b0.z,b0.w,b1.x,b1.y,b1.z,b1.w};
    float o[8];
    #pragma unroll
    for (int i = 0; i < 8; ++i){
        float ln = (v[i] - m) * inv * gg[i] + bb[i];
        o[i] = mode ? ln : (ln + xv[i]);
    }
    *(float4*)&g_x[base]     = make_float4(o[0],o[1],o[2],o[3]);
    *(float4*)&g_x[base + 4] = make_float4(o[4],o[5],o[6],o[7]);
}

// ---------------- fused flash attention ----------------
__global__ void __launch_bounds__(128) k_flash(){
    __shared__ __align__(16) float Qs[16][68];
    __shared__ __align__(16) float Ks[32][68];
    __shared__ __align__(16) float Vs[32][68];
    __shared__ float Ss[16][33];
    int tid = threadIdx.x;
    int b = blockIdx.y >> 2, h = blockIdx.y & 3;
    int q0 = blockIdx.x * 16;
    int qi = tid >> 3;
    int kc = (tid & 7) << 2;
    int dc = (tid & 7) << 3;

    for (int i = tid; i < 256; i += 128){
        int r = i >> 4, d4 = (i & 15) << 2;
        *(float4*)&Qs[r][d4] =
            *(const float4*)&g_xg[((size_t)(b*CT) + q0 + r)*CU3 + h*CHD + d4];
    }
    float acc[8];
    #pragma unroll
    for (int j = 0; j < 8; ++j) acc[j] = 0.f;
    float mrow = -3.0e38f, lrow = 0.f;

    for (int kt = 0; kt < CT; kt += 32){
        for (int i = tid; i < 512; i += 128){
            int r = i >> 4, d4 = (i & 15) << 2;
            size_t base = ((size_t)(b*CT) + kt + r)*CU3 + h*CHD + d4;
            *(float4*)&Ks[r][d4] = *(const float4*)&g_xg[base + CU];
            *(float4*)&Vs[r][d4] = *(const float4*)&g_xg[base + 2*CU];
        }
        __syncthreads();
        #pragma unroll
        for (int kk = 0; kk < 4; ++kk){
            int k = kc + kk;
            float s = 0.f;
            #pragma unroll
            for (int d = 0; d < 64; d += 4){
                float4 qv = *(const float4*)&Qs[qi][d];
                float4 kv = *(const float4*)&Ks[k][d];
                s += qv.x*kv.x + qv.y*kv.y + qv.z*kv.z + qv.w*kv.w;
            }
            Ss[qi][k] = s * 0.125f;
        }
        __syncthreads();
        float cm = -3.0e38f;
        #pragma unroll
        for (int j = 0; j < 32; ++j) cm = fmaxf(cm, Ss[qi][j]);
        float nm = fmaxf(mrow, cm);
        float corr = __expf(mrow - nm);
        lrow *= corr;
        #pragma unroll
        for (int j = 0; j < 8; ++j) acc[j] *= corr;
        #pragma unroll 4
        for (int j = 0; j < 32; ++j){
            float p = __expf(Ss[qi][j] - nm);
            lrow += p;
            float4 v0 = *(const float4*)&Vs[j][dc];
            float4 v1 = *(const float4*)&Vs[j][dc + 4];
            acc[0] += p*v0.x; acc[1] += p*v0.y; acc[2] += p*v0.z; acc[3] += p*v0.w;
            acc[4] += p*v1.x; acc[5] += p*v1.y; acc[6] += p*v1.z; acc[7] += p*v1.w;
        }
        mrow = nm;
        __syncthreads();
    }
    float inv = 1.f / lrow;
    size_t orow = ((size_t)(b*CT) + q0 + qi)*CU + h*CHD + dc;
    float4 o0 = make_float4(acc[0]*inv, acc[1]*inv, acc[2]*inv, acc[3]*inv);
    float4 o1 = make_float4(acc[4]*inv, acc[5]*inv, acc[6]*inv, acc[7]*inv);
    *(float4*)&g_tmp[orow]     = o0;
    *(float4*)&g_tmp[orow + 4] = o1;
}

// ---------------- mean pool over T + concat other ----------------
__global__ void k_pool(const float* __restrict__ other){
    int b = blockIdx.x, u = threadIdx.x;
    float s = 0.f;
    #pragma unroll 4
    for (int t = 0; t < CT; ++t) s += g_x[((size_t)b*CT + t)*CU + u];
    g_pool[b*(CU+CFO) + u] = s * (1.f/CT);
    if (u < CFO) g_pool[b*(CU+CFO) + CU + u] = other[b*CFO + u];
}

// ---------------- MLP head ----------------
__global__ void k_head(const float* __restrict__ m1W, const float* __restrict__ m1b,
                       const float* __restrict__ l1s, const float* __restrict__ l1b,
                       const float* __restrict__ m2W, const float* __restrict__ m2b,
                       const float* __restrict__ l2s, const float* __restrict__ l2b,
                       const float* __restrict__ oW, const float* __restrict__ ob,
                       float* __restrict__ out){
    __shared__ float ps[320];
    __shared__ float h1s[128];
    __shared__ float red[33];
    int b = blockIdx.x, j = threadIdx.x;
    for (int i = j; i < 320; i += 128) ps[i] = g_pool[b*320 + i];
    __syncthreads();
    float a = m1b[j];
    for (int k = 0; k < 320; ++k) a += ps[k] * m1W[k*128 + j];
    a = fmaxf(a, 0.f);
    float m = blk_sum(a, red) * (1.f/128.f);
    float d = a - m;
    float var = blk_sum(d*d, red) * (1.f/128.f);
    h1s[j] = d * rsqrtf(var + EPSF) * l1s[j] + l1b[j];
    __syncthreads();
    float a2 = 0.f;
    if (j < 64){
        a2 = m2b[j];
        for (int k = 0; k < 128; ++k) a2 += h1s[k] * m2W[k*64 + j];
        a2 = fmaxf(a2, 0.f);
    }
    float m2v = blk_sum((j < 64) ? a2 : 0.f, red) * (1.f/64.f);
    float d2 = a2 - m2v;
    float var2 = blk_sum((j < 64) ? d2*d2 : 0.f, red) * (1.f/64.f);
    float contrib = 0.f;
    if (j < 64){
        float h2 = d2 * rsqrtf(var2 + EPSF) * l2s[j] + l2b[j];
        contrib = h2 * oW[j];
    }
    float o = blk_sum(contrib, red);
    if (j == 0) out[b] = o + ob[0];
}

// ---------------- launch ----------------
extern "C" void kernel_launch(void* const* d_in, const int* in_sizes, int n_in,
                              void* d_out, int out_size){
    const float* cgm    = (const float*)d_in[0];
    const float* other  = (const float*)d_in[1];
    const float* d0_W   = (const float*)d_in[2];
    const float* d0_b   = (const float*)d_in[3];
    const float* ln0_s  = (const float*)d_in[4];
    const float* ln0_b  = (const float*)d_in[5];
    const float* gru_Wi = (const float*)d_in[6];
    const float* gru_bi = (const float*)d_in[7];
    const float* gru_Wh = (const float*)d_in[8];
    const float* gru_bhn= (const float*)d_in[9];
    const float* ln1_s  = (const float*)d_in[10];
    const float* ln1_b  = (const float*)d_in[11];
    const float* Wq     = (const float*)d_in[12];
    const float* bq     = (const float*)d_in[13];
    const float* Wk     = (const float*)d_in[14];
    const float* bk     = (const float*)d_in[15];
    const float* Wv     = (const float*)d_in[16];
    const float* bv     = (const float*)d_in[17];
    const float* Wo     = (const float*)d_in[18];
    const float* bo     = (const float*)d_in[19];
    const float* ln2_s  = (const float*)d_in[20];
    const float* ln2_b  = (const float*)d_in[21];
    const float* m1_W   = (const float*)d_in[22];
    const float* m1_b   = (const float*)d_in[23];
    const float* lm1_s  = (const float*)d_in[24];
    const float* lm1_b  = (const float*)d_in[25];
    const float* m2_W   = (const float*)d_in[26];
    const float* m2_b   = (const float*)d_in[27];
    const float* lm2_s  = (const float*)d_in[28];
    const float* lm2_b  = (const float*)d_in[29];
    const float* out_W  = (const float*)d_in[30];
    const float* out_b  = (const float*)d_in[31];
    float* outp = (float*)d_out;

    float *px, *ptmp, *pxg, *po, *pwq, *pbq;
    cudaGetSymbolAddress((void**)&px,   g_x);
    cudaGetSymbolAddress((void**)&ptmp, g_tmp);
    cudaGetSymbolAddress((void**)&pxg,  g_xg);
    cudaGetSymbolAddress((void**)&po,   g_o);
    cudaGetSymbolAddress((void**)&pwq,  g_wqkv);
    cudaGetSymbolAddress((void**)&pbq,  g_bqkv);

    const int GRU_SMEM = 8192*4 + 32*260*4;   // 32KB + 33.3KB
    cudaFuncSetAttribute(k_gru, cudaFuncAttributeMaxDynamicSharedMemorySize, GRU_SMEM);

    k_dense0<<<dim3(CB,4), 256>>>(cgm, d0_W, d0_b, ln0_s, ln0_b);

    for (int i = 0; i < 2; ++i){
        // xg = x @ Wi + bi  -> g_xg
        k_gemm_bias<<<dim3(CU3/128, CBT/128), 256>>>(px, gru_Wi + (size_t)i*CU*CU3,
                                                     gru_bi + i*CU3, pxg, CBT, CU3, CU);
        // GRU recurrence -> g_tmp
        k_gru_init<<<128, 256>>>();
        k_gru<<<128, 256, GRU_SMEM>>>(gru_Wh + (size_t)i*CU*CU3, gru_bhn + i*CU);
        // x = LN(ys) + x
        k_ln_res<<<CBT/8, 256>>>(ptmp, ln1_s + i*CU, ln1_b + i*CU, 0);
        // packed qkv GEMM -> g_xg
        k_pack<<<(CU*CU3 + 255)/256, 256>>>(Wq + (size_t)i*CU*CU, Wk + (size_t)i*CU*CU,
                                            Wv + (size_t)i*CU*CU, bq + i*CU, bk + i*CU, bv + i*CU);
        k_gemm_bias<<<dim3(CU3/128, CBT/128), 256>>>(px, pwq, pbq, pxg, CBT, CU3, CU);
        // fused attention -> g_tmp
        k_flash<<<dim3(CT/16, CB*CH), 128>>>();
        // out proj -> g_o, then x = LN(attn + x)
        k_gemm_bias<<<dim3(CU/128, CBT/128), 256>>>(ptmp, Wo + (size_t)i*CU*CU,
                                                    bo + i*CU, po, CBT, CU, CU);
        k_ln_res<<<CBT/8, 256>>>(po, ln2_s + i*CU, ln2_b + i*CU, 1);
    }

    k_pool<<<CB, 256>>>(other);
    k_head<<<CB, 128>>>(m1_W, m1_b, lm1_s, lm1_b, m2_W, m2_b, lm2_s, lm2_b, out_W, out_b, outp);
}